// round 1
// baseline (speedup 1.0000x reference)
#include <cuda_runtime.h>

#define NN 50000
#define EE 800000
#define D  128
#define H  8

// Persistent device scratch (zero-initialized at module load; the finalize
// kernel restores zeros after consuming, so every kernel_launch call starts
// from the same state -> deterministic + graph-replay safe).
__device__ float g_h  [NN * D];   // current layer features h = x @ W
__device__ float g_x2 [NN * D];   // layer-2 input (layer-1 activated output)
__device__ float g_acc[NN * D];   // unnormalized weighted aggregate (atomics)
__device__ float g_el [NN * H];
__device__ float g_er [NN * H];
__device__ float g_z  [NN * H];   // softmax denominators (atomics)

// ---------------------------------------------------------------------------
// GEMM + attention-coefficient kernel.
// Each warp processes 8 nodes at a time: x rows staged in smem, W streamed
// through L1 (64 KB, stays resident), 8x reuse of each W element.
// Epilogue computes el/er per head via intra-quad shuffle reduction.
// ---------------------------------------------------------------------------
__global__ __launch_bounds__(128) void gat_gemm(
    const float* __restrict__ xin, const float* __restrict__ W,
    const float* __restrict__ al,  const float* __restrict__ ar, int layer)
{
    __shared__ float xs[4 * 8 * D];   // 16 KB: 4 warps x 8 nodes x 128 floats

    const float* x = (layer == 0) ? xin : g_x2;

    int tid  = threadIdx.x;
    int warp = tid >> 5;
    int lane = tid & 31;
    int head = lane >> 2;   // 4 lanes per head (4 cols each = 16 cols/head)
    int sub  = lane & 3;

    float4 alv = *(const float4*)(al + head * 16 + sub * 4);
    float4 arv = *(const float4*)(ar + head * 16 + sub * 4);

    const float4* W4 = (const float4*)W;
    float* xw = xs + warp * 8 * D;

    for (int base = (blockIdx.x * 4 + warp) * 8; base < NN;
         base += gridDim.x * 4 * 8)
    {
        // Stage 8 x-rows (N is divisible by 8, so no tail guard needed)
        #pragma unroll
        for (int i = 0; i < 8; i++)
            ((float4*)(xw + i * D))[lane] =
                ((const float4*)(x + (size_t)(base + i) * D))[lane];
        __syncwarp();

        float4 acc[8];
        #pragma unroll
        for (int i = 0; i < 8; i++) acc[i] = make_float4(0.f, 0.f, 0.f, 0.f);

        #pragma unroll 4
        for (int k = 0; k < D; k++) {
            float4 w4 = __ldg(W4 + k * (D / 4) + lane);
            #pragma unroll
            for (int i = 0; i < 8; i++) {
                float xk = xw[i * D + k];
                acc[i].x = fmaf(xk, w4.x, acc[i].x);
                acc[i].y = fmaf(xk, w4.y, acc[i].y);
                acc[i].z = fmaf(xk, w4.z, acc[i].z);
                acc[i].w = fmaf(xk, w4.w, acc[i].w);
            }
        }

        #pragma unroll
        for (int i = 0; i < 8; i++) {
            int n = base + i;
            ((float4*)(g_h + (size_t)n * D))[lane] = acc[i];
            float pel = acc[i].x * alv.x + acc[i].y * alv.y +
                        acc[i].z * alv.z + acc[i].w * alv.w;
            float per = acc[i].x * arv.x + acc[i].y * arv.y +
                        acc[i].z * arv.z + acc[i].w * arv.w;
            pel += __shfl_xor_sync(0xffffffffu, pel, 1);
            pel += __shfl_xor_sync(0xffffffffu, pel, 2);
            per += __shfl_xor_sync(0xffffffffu, per, 1);
            per += __shfl_xor_sync(0xffffffffu, per, 2);
            if (sub == 0) {
                g_el[n * H + head] = pel;
                g_er[n * H + head] = per;
            }
        }
        __syncwarp();
    }
}

// ---------------------------------------------------------------------------
// Fused edge pass: per edge, compute a = exp(leakyrelu(el[src]+er[dst], 0.2))
// (no segment_max needed: softmax is shift-invariant and logits are O(5)),
// then z[dst] += a and acc[dst] += a * h[src].
// One warp = EPW edges (batched loads for MLP). h gather + acc scatter are
// both L2-resident (25.6 MB tables). red.global.add.v4.f32 for the scatter.
// ---------------------------------------------------------------------------
#define EPW 4
__global__ __launch_bounds__(256) void gat_edge(
    const int* __restrict__ src, const int* __restrict__ dst)
{
    int wg   = blockIdx.x * 8 + (threadIdx.x >> 5);
    int lane = threadIdx.x & 31;
    int e0   = wg * EPW;
    if (e0 >= EE) return;
    int head = lane >> 2;

    int s[EPW], d[EPW];
    #pragma unroll
    for (int i = 0; i < EPW; i++) {
        int e = e0 + i;
        if (e < EE) { s[i] = src[e]; d[i] = dst[e]; }
        else        { s[i] = -1;      d[i] = 0; }
    }

    float a[EPW];
    float4 hv[EPW];
    #pragma unroll
    for (int i = 0; i < EPW; i++) {
        if (s[i] >= 0) {
            float ev = __ldg(g_el + s[i] * H + head) +
                       __ldg(g_er + d[i] * H + head);
            ev   = ev > 0.f ? ev : 0.2f * ev;
            a[i] = __expf(ev);
            hv[i] = *(const float4*)(g_h + (size_t)s[i] * D + lane * 4);
        }
    }

    #pragma unroll
    for (int i = 0; i < EPW; i++) {
        if (s[i] >= 0) {
            if ((lane & 3) == 0) atomicAdd(&g_z[d[i] * H + head], a[i]);
            float vx = a[i] * hv[i].x;
            float vy = a[i] * hv[i].y;
            float vz = a[i] * hv[i].z;
            float vw = a[i] * hv[i].w;
            asm volatile(
                "red.global.add.v4.f32 [%0], {%1, %2, %3, %4};"
                :: "l"(g_acc + (size_t)d[i] * D + lane * 4),
                   "f"(vx), "f"(vy), "f"(vz), "f"(vw)
                : "memory");
        }
    }
}

// ---------------------------------------------------------------------------
// Finalize: out = acc / z (per head), optional leaky_relu(0.01).
// Also restores acc and z to zero for the next layer / next graph replay.
// One block per node (128 threads = 128 cols).
// layer==0: write g_x2 with activation; layer==1: write 'out', no activation.
// ---------------------------------------------------------------------------
__global__ __launch_bounds__(128) void gat_finalize(float* __restrict__ out,
                                                    int layer)
{
    __shared__ float zs[H];
    int n = blockIdx.x;
    int c = threadIdx.x;
    if (c < H) zs[c] = g_z[n * H + c];
    __syncthreads();

    float zz = zs[c >> 4];
    float v  = (zz > 0.f) ? g_acc[n * D + c] / zz : 0.f;

    if (layer == 0) {
        v = v > 0.f ? v : 0.01f * v;
        g_x2[n * D + c] = v;
    } else {
        out[n * D + c] = v;
    }

    // restore zeros for next use (keeps determinism across graph replays)
    g_acc[n * D + c] = 0.f;
    if (c < H) g_z[n * H + c] = 0.f;
}

// ---------------------------------------------------------------------------
extern "C" void kernel_launch(void* const* d_in, const int* in_sizes, int n_in,
                              void* d_out, int out_size)
{
    const float* n_feat = (const float*)d_in[0];
    const int*   src    = (const int*)  d_in[1];
    const int*   dst    = (const int*)  d_in[2];
    const float* W1     = (const float*)d_in[3];
    const float* al1    = (const float*)d_in[4];
    const float* ar1    = (const float*)d_in[5];
    const float* W2     = (const float*)d_in[6];
    const float* al2    = (const float*)d_in[7];
    const float* ar2    = (const float*)d_in[8];
    float* out = (float*)d_out;

    const int gemm_grid = (NN + 31) / 32;          // 32 nodes per block
    const int edge_grid = (EE + 8 * EPW - 1) / (8 * EPW);
    const int fin_grid  = NN;

    // Layer 1
    gat_gemm<<<gemm_grid, 128>>>(n_feat, W1, al1, ar1, 0);
    gat_edge<<<edge_grid, 256>>>(src, dst);
    gat_finalize<<<fin_grid, 128>>>(out, 0);   // writes g_x2 (+act), zeroes acc/z

    // Layer 2
    gat_gemm<<<gemm_grid, 128>>>(n_feat, W2, al2, ar2, 1);
    gat_edge<<<edge_grid, 256>>>(src, dst);
    gat_finalize<<<fin_grid, 128>>>(out, 1);   // writes d_out, zeroes acc/z
}

// round 3
// speedup vs baseline: 1.5795x; 1.5795x over previous
#include <cuda_runtime.h>

#define NN 50000
#define EE 800000
#define D  128
#define H  8
#define NBLK 49   // ceil(NN / 1024)

// Persistent device scratch.
__device__ float g_h   [NN * D];   // h = x @ W (current layer)
__device__ float g_x2  [NN * D];   // layer-2 input (activated layer-1 output)
__device__ float g_el  [NN * H];
__device__ float g_er  [NN * H];
__device__ int   g_deg [NN];       // in-degree histogram
__device__ int   g_off [NN];       // exclusive prefix (CSR row offsets)
__device__ int   g_pos [NN];       // running write cursor for scatter
__device__ int   g_ssrc[EE];       // src ids sorted by dst
__device__ int   g_bsum[NBLK];     // scan block sums

// ---------------------------------------------------------------------------
// CSR build: histogram -> 3-kernel scan -> scatter. Graph is layer-invariant,
// so this runs once per launch and serves both layers.
// ---------------------------------------------------------------------------
__global__ __launch_bounds__(256) void k_zero_deg()
{
    int i = blockIdx.x * 256 + threadIdx.x;
    if (i < NN) g_deg[i] = 0;
}

__global__ __launch_bounds__(256) void k_count(const int* __restrict__ dst)
{
    int e = blockIdx.x * 256 + threadIdx.x;
    if (e < EE) atomicAdd(&g_deg[dst[e]], 1);
}

__global__ __launch_bounds__(1024) void k_scan1()
{
    __shared__ int wsum[32];
    int i = blockIdx.x * 1024 + threadIdx.x;
    int v = (i < NN) ? g_deg[i] : 0;
    int lane = threadIdx.x & 31, w = threadIdx.x >> 5;
    int x = v;
    #pragma unroll
    for (int o = 1; o < 32; o <<= 1) {
        int t = __shfl_up_sync(0xffffffffu, x, o);
        if (lane >= o) x += t;
    }
    if (lane == 31) wsum[w] = x;
    __syncthreads();
    if (w == 0) {
        int s = wsum[lane];
        #pragma unroll
        for (int o = 1; o < 32; o <<= 1) {
            int t = __shfl_up_sync(0xffffffffu, s, o);
            if (lane >= o) s += t;
        }
        wsum[lane] = s;
    }
    __syncthreads();
    int excl = x - v + (w > 0 ? wsum[w - 1] : 0);
    if (i < NN) g_off[i] = excl;
    if (threadIdx.x == 1023) g_bsum[blockIdx.x] = wsum[31];
}

__global__ void k_scan2()
{
    if (threadIdx.x == 0) {
        int run = 0;
        for (int i = 0; i < NBLK; i++) {
            int t = g_bsum[i];
            g_bsum[i] = run;
            run += t;
        }
    }
}

__global__ __launch_bounds__(1024) void k_scan3()
{
    int i = blockIdx.x * 1024 + threadIdx.x;
    if (i < NN) {
        int o = g_off[i] + g_bsum[blockIdx.x];
        g_off[i] = o;
        g_pos[i] = o;
    }
}

__global__ __launch_bounds__(256) void k_scatter(const int* __restrict__ src,
                                                const int* __restrict__ dst)
{
    int e = blockIdx.x * 256 + threadIdx.x;
    if (e < EE) {
        int p = atomicAdd(&g_pos[dst[e]], 1);
        g_ssrc[p] = src[e];
    }
}

// ---------------------------------------------------------------------------
// GEMM + attention-coefficient kernel (R1-measured: 62us, fma-issue limited;
// restructure queued for a later round).
// ---------------------------------------------------------------------------
__global__ __launch_bounds__(128) void gat_gemm(
    const float* __restrict__ xin, const float* __restrict__ W,
    const float* __restrict__ al,  const float* __restrict__ ar, int layer)
{
    __shared__ float xs[4 * 8 * D];

    const float* x = (layer == 0) ? xin : g_x2;

    int tid  = threadIdx.x;
    int warp = tid >> 5;
    int lane = tid & 31;
    int head = lane >> 2;
    int sub  = lane & 3;

    float4 alv = *(const float4*)(al + head * 16 + sub * 4);
    float4 arv = *(const float4*)(ar + head * 16 + sub * 4);

    const float4* W4 = (const float4*)W;
    float* xw = xs + warp * 8 * D;

    for (int base = (blockIdx.x * 4 + warp) * 8; base < NN;
         base += gridDim.x * 4 * 8)
    {
        #pragma unroll
        for (int i = 0; i < 8; i++)
            ((float4*)(xw + i * D))[lane] =
                ((const float4*)(x + (size_t)(base + i) * D))[lane];
        __syncwarp();

        float4 acc[8];
        #pragma unroll
        for (int i = 0; i < 8; i++) acc[i] = make_float4(0.f, 0.f, 0.f, 0.f);

        #pragma unroll 4
        for (int k = 0; k < D; k++) {
            float4 w4 = __ldg(W4 + k * (D / 4) + lane);
            #pragma unroll
            for (int i = 0; i < 8; i++) {
                float xk = xw[i * D + k];
                acc[i].x = fmaf(xk, w4.x, acc[i].x);
                acc[i].y = fmaf(xk, w4.y, acc[i].y);
                acc[i].z = fmaf(xk, w4.z, acc[i].z);
                acc[i].w = fmaf(xk, w4.w, acc[i].w);
            }
        }

        #pragma unroll
        for (int i = 0; i < 8; i++) {
            int n = base + i;
            ((float4*)(g_h + (size_t)n * D))[lane] = acc[i];
            float pel = acc[i].x * alv.x + acc[i].y * alv.y +
                        acc[i].z * alv.z + acc[i].w * alv.w;
            float per = acc[i].x * arv.x + acc[i].y * arv.y +
                        acc[i].z * arv.z + acc[i].w * arv.w;
            pel += __shfl_xor_sync(0xffffffffu, pel, 1);
            pel += __shfl_xor_sync(0xffffffffu, pel, 2);
            per += __shfl_xor_sync(0xffffffffu, per, 1);
            per += __shfl_xor_sync(0xffffffffu, per, 2);
            if (sub == 0) {
                g_el[n * H + head] = pel;
                g_er[n * H + head] = per;
            }
        }
        __syncwarp();
    }
}

// ---------------------------------------------------------------------------
// Gather-aggregate: one warp per destination node. Iterates the node's sorted
// incoming edges; z and acc live in registers; softmax division, activation
// and output store fused in. No atomics, no g_acc/g_z, no finalize pass.
// Softmax max-shift skipped (logits are O(3); exp never overflows fp32).
// ---------------------------------------------------------------------------
__global__ __launch_bounds__(256) void gat_gather(float* __restrict__ out,
                                                  int layer)
{
    int n = blockIdx.x * 8 + (threadIdx.x >> 5);
    if (n >= NN) return;
    int lane = threadIdx.x & 31;
    int head = lane >> 2;

    int start = g_off[n];
    int deg   = g_deg[n];
    float er_d = __ldg(g_er + n * H + head);

    float4 acc = make_float4(0.f, 0.f, 0.f, 0.f);
    float  z   = 0.f;

    #pragma unroll 4
    for (int j = 0; j < deg; j++) {
        int s = __ldg(g_ssrc + start + j);   // uniform across warp -> 1 txn
        float e = __ldg(g_el + s * H + head) + er_d;
        e = e > 0.f ? e : 0.2f * e;
        float a = __expf(e);
        z += a;
        float4 hv = *(const float4*)(g_h + (size_t)s * D + lane * 4);
        acc.x = fmaf(a, hv.x, acc.x);
        acc.y = fmaf(a, hv.y, acc.y);
        acc.z = fmaf(a, hv.z, acc.z);
        acc.w = fmaf(a, hv.w, acc.w);
    }

    float inv = (z > 0.f) ? 1.f / z : 0.f;
    float4 v = make_float4(acc.x * inv, acc.y * inv, acc.z * inv, acc.w * inv);

    if (layer == 0) {
        v.x = v.x > 0.f ? v.x : 0.01f * v.x;
        v.y = v.y > 0.f ? v.y : 0.01f * v.y;
        v.z = v.z > 0.f ? v.z : 0.01f * v.z;
        v.w = v.w > 0.f ? v.w : 0.01f * v.w;
        *(float4*)(g_x2 + (size_t)n * D + lane * 4) = v;
    } else {
        *(float4*)(out + (size_t)n * D + lane * 4) = v;
    }
}

// ---------------------------------------------------------------------------
extern "C" void kernel_launch(void* const* d_in, const int* in_sizes, int n_in,
                              void* d_out, int out_size)
{
    const float* n_feat = (const float*)d_in[0];
    const int*   src    = (const int*)  d_in[1];
    const int*   dst    = (const int*)  d_in[2];
    const float* W1     = (const float*)d_in[3];
    const float* al1    = (const float*)d_in[4];
    const float* ar1    = (const float*)d_in[5];
    const float* W2     = (const float*)d_in[6];
    const float* al2    = (const float*)d_in[7];
    const float* ar2    = (const float*)d_in[8];
    float* out = (float*)d_out;

    const int gemm_grid = (NN + 31) / 32;
    const int gath_grid = (NN + 7) / 8;

    // CSR build (once; graph shared by both layers)
    k_zero_deg<<<(NN + 255) / 256, 256>>>();
    k_count   <<<(EE + 255) / 256, 256>>>(dst);
    k_scan1   <<<NBLK, 1024>>>();
    k_scan2   <<<1, 32>>>();
    k_scan3   <<<NBLK, 1024>>>();
    k_scatter <<<(EE + 255) / 256, 256>>>(src, dst);

    // Layer 1
    gat_gemm  <<<gemm_grid, 128>>>(n_feat, W1, al1, ar1, 0);
    gat_gather<<<gath_grid, 256>>>(out, 0);   // writes g_x2 (+act)

    // Layer 2
    gat_gemm  <<<gemm_grid, 128>>>(n_feat, W2, al2, ar2, 1);
    gat_gather<<<gath_grid, 256>>>(out, 1);   // writes d_out
}

// round 4
// speedup vs baseline: 1.7144x; 1.0854x over previous
#include <cuda_runtime.h>

#define NN 50000
#define EE 800000
#define D  128
#define H  8
#define NBLK 49   // ceil(NN / 1024)

typedef unsigned long long u64;

// Persistent device scratch.
__device__ float g_h   [NN * D];   // h = x @ W (current layer)
__device__ float g_x2  [NN * D];   // layer-2 input (activated layer-1 output)
__device__ float g_el  [NN * H];
__device__ float g_er  [NN * H];
__device__ int   g_deg [NN];       // in-degree histogram
__device__ int   g_off [NN];       // exclusive prefix (CSR row offsets)
__device__ int   g_pos [NN];       // running write cursor for scatter
__device__ int   g_ssrc[EE];       // src ids sorted by dst
__device__ int   g_bsum[NBLK];     // scan block sums

// ---- packed f32x2 helpers (Blackwell FFMA2: 2 fp32 MACs per issue slot) ----
__device__ __forceinline__ u64 fma2(u64 a, u64 b, u64 c) {
    u64 d;
    asm("fma.rn.f32x2 %0, %1, %2, %3;" : "=l"(d) : "l"(a), "l"(b), "l"(c));
    return d;
}
__device__ __forceinline__ u64 pack2(float lo, float hi) {
    u64 d;
    asm("mov.b64 %0, {%1, %2};" : "=l"(d) : "f"(lo), "f"(hi));
    return d;
}
__device__ __forceinline__ void unpack2(float& lo, float& hi, u64 v) {
    asm("mov.b64 {%0, %1}, %2;" : "=f"(lo), "=f"(hi) : "l"(v));
}

// ---------------------------------------------------------------------------
// CSR build: histogram -> 3-kernel scan -> scatter. Once per launch; graph is
// layer-invariant so it serves both layers.
// ---------------------------------------------------------------------------
__global__ __launch_bounds__(256) void k_zero_deg()
{
    int i = blockIdx.x * 256 + threadIdx.x;
    if (i < NN) g_deg[i] = 0;
}

__global__ __launch_bounds__(256) void k_count(const int* __restrict__ dst)
{
    int e = blockIdx.x * 256 + threadIdx.x;
    if (e < EE) atomicAdd(&g_deg[dst[e]], 1);
}

__global__ __launch_bounds__(1024) void k_scan1()
{
    __shared__ int wsum[32];
    int i = blockIdx.x * 1024 + threadIdx.x;
    int v = (i < NN) ? g_deg[i] : 0;
    int lane = threadIdx.x & 31, w = threadIdx.x >> 5;
    int x = v;
    #pragma unroll
    for (int o = 1; o < 32; o <<= 1) {
        int t = __shfl_up_sync(0xffffffffu, x, o);
        if (lane >= o) x += t;
    }
    if (lane == 31) wsum[w] = x;
    __syncthreads();
    if (w == 0) {
        int s = wsum[lane];
        #pragma unroll
        for (int o = 1; o < 32; o <<= 1) {
            int t = __shfl_up_sync(0xffffffffu, s, o);
            if (lane >= o) s += t;
        }
        wsum[lane] = s;
    }
    __syncthreads();
    int excl = x - v + (w > 0 ? wsum[w - 1] : 0);
    if (i < NN) g_off[i] = excl;
    if (threadIdx.x == 1023) g_bsum[blockIdx.x] = wsum[31];
}

// Parallel scan of NBLK(=49) block sums: 64 threads, shfl + one smem hop.
// (Replaces the R3 single-thread serial loop measured at 5.7us.)
__global__ __launch_bounds__(64) void k_scan2()
{
    __shared__ int w0sum;
    int t = threadIdx.x, lane = t & 31, w = t >> 5;
    int v = (t < NBLK) ? g_bsum[t] : 0;
    int x = v;
    #pragma unroll
    for (int o = 1; o < 32; o <<= 1) {
        int s = __shfl_up_sync(0xffffffffu, x, o);
        if (lane >= o) x += s;
    }
    if (w == 0 && lane == 31) w0sum = x;
    __syncthreads();
    int excl = x - v + (w ? w0sum : 0);
    if (t < NBLK) g_bsum[t] = excl;
}

__global__ __launch_bounds__(1024) void k_scan3()
{
    int i = blockIdx.x * 1024 + threadIdx.x;
    if (i < NN) {
        int o = g_off[i] + g_bsum[blockIdx.x];
        g_off[i] = o;
        g_pos[i] = o;
    }
}

__global__ __launch_bounds__(256) void k_scatter(const int* __restrict__ src,
                                                const int* __restrict__ dst)
{
    int e = blockIdx.x * 256 + threadIdx.x;
    if (e < EE) {
        int p = atomicAdd(&g_pos[dst[e]], 1);
        g_ssrc[p] = src[e];
    }
}

// ---------------------------------------------------------------------------
// GEMM + attention-coefficient kernel. Per-warp 8 nodes x 128 cols.
// Inner loop k-unrolled x4: 4 batched LDG.128 of W (MLP=4), LDS.128 x reads,
// all math via packed fma.rn.f32x2 (2 MACs per FFMA2 issue slot -> halves the
// fp32 math floor vs scalar 3-reg FFMA at rt_SMSP=2).
// ---------------------------------------------------------------------------
__global__ __launch_bounds__(128) void gat_gemm(
    const float* __restrict__ xin, const float* __restrict__ W,
    const float* __restrict__ al,  const float* __restrict__ ar, int layer)
{
    __shared__ float xs[4 * 8 * D];   // 16 KB

    const float* x = (layer == 0) ? xin : g_x2;

    int tid  = threadIdx.x;
    int warp = tid >> 5;
    int lane = tid & 31;
    int head = lane >> 2;
    int sub  = lane & 3;

    float4 alv = *(const float4*)(al + head * 16 + sub * 4);
    float4 arv = *(const float4*)(ar + head * 16 + sub * 4);

    const float4* W4 = (const float4*)W;
    float* xw = xs + warp * 8 * D;

    for (int base = (blockIdx.x * 4 + warp) * 8; base < NN;
         base += gridDim.x * 4 * 8)
    {
        #pragma unroll
        for (int i = 0; i < 8; i++)
            ((float4*)(xw + i * D))[lane] =
                ((const float4*)(x + (size_t)(base + i) * D))[lane];
        __syncwarp();

        u64 a0[8], a1[8];   // cols (0,1) and (2,3) of this lane's 4 columns
        #pragma unroll
        for (int i = 0; i < 8; i++) { a0[i] = 0ull; a1[i] = 0ull; }

        for (int k0 = 0; k0 < D; k0 += 4) {
            // batched independent W loads -> MLP 4
            float4 w0 = __ldg(W4 + (k0 + 0) * (D / 4) + lane);
            float4 w1 = __ldg(W4 + (k0 + 1) * (D / 4) + lane);
            float4 w2 = __ldg(W4 + (k0 + 2) * (D / 4) + lane);
            float4 w3 = __ldg(W4 + (k0 + 3) * (D / 4) + lane);
            u64 wl0 = pack2(w0.x, w0.y), wh0 = pack2(w0.z, w0.w);
            u64 wl1 = pack2(w1.x, w1.y), wh1 = pack2(w1.z, w1.w);
            u64 wl2 = pack2(w2.x, w2.y), wh2 = pack2(w2.z, w2.w);
            u64 wl3 = pack2(w3.x, w3.y), wh3 = pack2(w3.z, w3.w);

            #pragma unroll
            for (int i = 0; i < 8; i++) {
                float4 xv = *(const float4*)(xw + i * D + k0);  // LDS.128
                u64 xx;
                xx = pack2(xv.x, xv.x);
                a0[i] = fma2(xx, wl0, a0[i]); a1[i] = fma2(xx, wh0, a1[i]);
                xx = pack2(xv.y, xv.y);
                a0[i] = fma2(xx, wl1, a0[i]); a1[i] = fma2(xx, wh1, a1[i]);
                xx = pack2(xv.z, xv.z);
                a0[i] = fma2(xx, wl2, a0[i]); a1[i] = fma2(xx, wh2, a1[i]);
                xx = pack2(xv.w, xv.w);
                a0[i] = fma2(xx, wl3, a0[i]); a1[i] = fma2(xx, wh3, a1[i]);
            }
        }

        #pragma unroll
        for (int i = 0; i < 8; i++) {
            int n = base + i;
            float c0, c1, c2, c3;
            unpack2(c0, c1, a0[i]);
            unpack2(c2, c3, a1[i]);
            float4 hv = make_float4(c0, c1, c2, c3);
            ((float4*)(g_h + (size_t)n * D))[lane] = hv;

            float pel = c0 * alv.x + c1 * alv.y + c2 * alv.z + c3 * alv.w;
            float per = c0 * arv.x + c1 * arv.y + c2 * arv.z + c3 * arv.w;
            pel += __shfl_xor_sync(0xffffffffu, pel, 1);
            pel += __shfl_xor_sync(0xffffffffu, pel, 2);
            per += __shfl_xor_sync(0xffffffffu, per, 1);
            per += __shfl_xor_sync(0xffffffffu, per, 2);
            if (sub == 0) {
                g_el[n * H + head] = pel;
                g_er[n * H + head] = per;
            }
        }
        __syncwarp();
    }
}

// ---------------------------------------------------------------------------
// Gather-aggregate: one warp per destination node; z and acc in registers,
// softmax division + activation + store fused. No atomics. L2-BW bound.
// ---------------------------------------------------------------------------
__global__ __launch_bounds__(256) void gat_gather(float* __restrict__ out,
                                                  int layer)
{
    int n = blockIdx.x * 8 + (threadIdx.x >> 5);
    if (n >= NN) return;
    int lane = threadIdx.x & 31;
    int head = lane >> 2;

    int start = g_off[n];
    int deg   = g_deg[n];
    float er_d = __ldg(g_er + n * H + head);

    float4 acc = make_float4(0.f, 0.f, 0.f, 0.f);
    float  z   = 0.f;

    #pragma unroll 4
    for (int j = 0; j < deg; j++) {
        int s = __ldg(g_ssrc + start + j);   // uniform across warp
        float e = __ldg(g_el + s * H + head) + er_d;
        e = e > 0.f ? e : 0.2f * e;
        float a = __expf(e);
        z += a;
        float4 hv = *(const float4*)(g_h + (size_t)s * D + lane * 4);
        acc.x = fmaf(a, hv.x, acc.x);
        acc.y = fmaf(a, hv.y, acc.y);
        acc.z = fmaf(a, hv.z, acc.z);
        acc.w = fmaf(a, hv.w, acc.w);
    }

    float inv = (z > 0.f) ? 1.f / z : 0.f;
    float4 v = make_float4(acc.x * inv, acc.y * inv, acc.z * inv, acc.w * inv);

    if (layer == 0) {
        v.x = v.x > 0.f ? v.x : 0.01f * v.x;
        v.y = v.y > 0.f ? v.y : 0.01f * v.y;
        v.z = v.z > 0.f ? v.z : 0.01f * v.z;
        v.w = v.w > 0.f ? v.w : 0.01f * v.w;
        *(float4*)(g_x2 + (size_t)n * D + lane * 4) = v;
    } else {
        *(float4*)(out + (size_t)n * D + lane * 4) = v;
    }
}

// ---------------------------------------------------------------------------
extern "C" void kernel_launch(void* const* d_in, const int* in_sizes, int n_in,
                              void* d_out, int out_size)
{
    const float* n_feat = (const float*)d_in[0];
    const int*   src    = (const int*)  d_in[1];
    const int*   dst    = (const int*)  d_in[2];
    const float* W1     = (const float*)d_in[3];
    const float* al1    = (const float*)d_in[4];
    const float* ar1    = (const float*)d_in[5];
    const float* W2     = (const float*)d_in[6];
    const float* al2    = (const float*)d_in[7];
    const float* ar2    = (const float*)d_in[8];
    float* out = (float*)d_out;

    const int gemm_grid = (NN + 31) / 32;
    const int gath_grid = (NN + 7) / 8;

    // CSR build (once; graph shared by both layers)
    k_zero_deg<<<(NN + 255) / 256, 256>>>();
    k_count   <<<(EE + 255) / 256, 256>>>(dst);
    k_scan1   <<<NBLK, 1024>>>();
    k_scan2   <<<1, 64>>>();
    k_scan3   <<<NBLK, 1024>>>();
    k_scatter <<<(EE + 255) / 256, 256>>>(src, dst);

    // Layer 1
    gat_gemm  <<<gemm_grid, 128>>>(n_feat, W1, al1, ar1, 0);
    gat_gather<<<gath_grid, 256>>>(out, 0);   // writes g_x2 (+act)

    // Layer 2
    gat_gemm  <<<gemm_grid, 128>>>(n_feat, W2, al2, ar2, 1);
    gat_gather<<<gath_grid, 256>>>(out, 1);   // writes d_out
}